// round 9
// baseline (speedup 1.0000x reference)
#include <cuda_runtime.h>
#include <math.h>

#define NU 50000
#define NI 40000
#define NN 90000
#define D  64
#define EH 500000
#define E  1000000
#define OD 192

typedef unsigned long long ull;

// ------------------- scratch (static device globals; no allocation) -------------------
__device__ int   g_is64;
__device__ int   g_src[E];
__device__ int   g_dst[E];
__device__ int   g_degG[NN];
__device__ int   g_offG[NN];
__device__ int   g_curG[NN];
__device__ int   g_bsum[128];
__device__ int   g_csrG_src[E];
__device__ float g_e[E];           // exp(logit) per CSR slot (final GAT only)
__device__ float g_alpha[2 * E];   // [mod*E + slot] final-GAT half-alpha
__device__ float g_wc[E];          // combined SAGE weight per CSR slot
__device__ __align__(16) float g_xm[2 * NN * D];
__device__ __align__(16) float g_hx[2 * NN * D];

__device__ __forceinline__ float lrelu(float v) { return v >= 0.f ? v : 0.01f * v; }
static inline int divup(int a, int b) { return (a + b - 1) / b; }

__device__ __forceinline__ void ffma2(ull& d, ull a, ull b) {
    asm("fma.rn.f32x2 %0, %1, %2, %0;" : "+l"(d) : "l"(a), "l"(b));
}
__device__ __forceinline__ ull pack2(float lo, float hi) {
    ull r;
    asm("mov.b64 %0, {%1, %2};" : "=l"(r) : "f"(lo), "f"(hi));
    return r;
}
__device__ __forceinline__ float2 unpack2(ull v) {
    float2 r;
    asm("mov.b64 {%0, %1}, %2;" : "=f"(r.x), "=f"(r.y) : "l"(v));
    return r;
}

// ------------------- edge dtype sniff -------------------
__global__ void k_sniff(const int* __restrict__ ei32) {
    int lane = threadIdx.x;
    int nz = 0;
    for (int i = lane; i < 512; i += 32)
        if (ei32[2 * i + 1] != 0) nz++;
    #pragma unroll
    for (int o = 16; o; o >>= 1) nz += __shfl_xor_sync(0xffffffffu, nz, o);
    if (lane == 0) g_is64 = (nz == 0) ? 1 : 0;
}

// ------------------- graph construction -------------------
__global__ void k_zero() {
    int i = blockIdx.x * blockDim.x + threadIdx.x;
    if (i < NN) g_degG[i] = 0;
}

__global__ void k_build(const void* __restrict__ eiRaw) {
    int i = blockIdx.x * blockDim.x + threadIdx.x;
    if (i >= E) return;
    int s, d;
    if (g_is64) {
        const long long* e64 = (const long long*)eiRaw;
        s = (int)e64[i];
        d = (int)e64[E + i];
    } else {
        const int* e32 = (const int*)eiRaw;
        s = e32[i];
        d = e32[E + i];
    }
    if ((unsigned)s >= NN) s = 0;
    if ((unsigned)d >= NN) d = 0;
    g_src[i] = s;
    g_dst[i] = d;
    atomicAdd(&g_degG[d], 1);
}

__global__ void k_scan1() {
    __shared__ int sh[1024];
    int t = threadIdx.x;
    int i = blockIdx.x * 1024 + t;
    int v = (i < NN) ? g_degG[i] : 0;
    sh[t] = v;
    __syncthreads();
    for (int st = 1; st < 1024; st <<= 1) {
        int x = (t >= st) ? sh[t - st] : 0;
        __syncthreads();
        sh[t] += x;
        __syncthreads();
    }
    if (i < NN) g_offG[i] = sh[t] - v;
    if (t == 1023) g_bsum[blockIdx.x] = sh[1023];
}

__global__ void k_scan2(int nb) {
    __shared__ int sh[128];
    int t = threadIdx.x;
    int v = (t < nb) ? g_bsum[t] : 0;
    sh[t] = v;
    __syncthreads();
    for (int st = 1; st < 128; st <<= 1) {
        int x = (t >= st) ? sh[t - st] : 0;
        __syncthreads();
        sh[t] += x;
        __syncthreads();
    }
    if (t < nb) g_bsum[t] = sh[t] - v;
}

__global__ void k_scan3() {
    int i = blockIdx.x * 1024 + threadIdx.x;
    if (i < NN) {
        int o = g_offG[i] + g_bsum[blockIdx.x];
        g_offG[i] = o;
        g_curG[i] = o;
    }
}

__global__ void k_place() {
    int i = blockIdx.x * blockDim.x + threadIdx.x;
    if (i >= E) return;
    int p = atomicAdd(&g_curG[g_dst[i]], 1);
    if ((unsigned)p < E) g_csrG_src[p] = g_src[i];
}

// ------------------- fused GEMM + bias + leaky + l2norm -------------------
// Tile 128x64, K-tile 32. 256 threads; 8x4 thread tile via fma.rn.f32x2; B pre-splatted.
__global__ __launch_bounds__(256) void k_gemm_fused(
    const float* __restrict__ A, const float* __restrict__ Bm,
    const float* __restrict__ bias, int mod, int K)
{
    float* C = g_xm + (size_t)mod * NN * D + (size_t)NU * D;
    __shared__ __align__(16) float sA[32][132];  // [k][m]
    __shared__ __align__(16) ull  sB2[32][66];   // [k][slot], slot = j*16 + tx, both halves = B[k][tx*4+j]
    int t  = threadIdx.x;
    int tx = t & 15;
    int ty = t >> 4;
    int m0 = blockIdx.x * 128;

    int ak4 = t & 7;
    int ar  = t >> 3;
    int bn4 = t & 15;
    int bkr = t >> 4;

    ull acc[4][4];
    #pragma unroll
    for (int i = 0; i < 4; i++)
        #pragma unroll
        for (int j = 0; j < 4; j++) acc[i][j] = 0ull;

    for (int kt = 0; kt < K; kt += 32) {
        #pragma unroll
        for (int p = 0; p < 4; p++) {
            int m = ar + p * 32;
            int gm = m0 + m;
            float4 av = make_float4(0.f, 0.f, 0.f, 0.f);
            if (gm < NI) av = *(const float4*)&A[(size_t)gm * K + kt + ak4 * 4];
            sA[ak4 * 4 + 0][m] = av.x;
            sA[ak4 * 4 + 1][m] = av.y;
            sA[ak4 * 4 + 2][m] = av.z;
            sA[ak4 * 4 + 3][m] = av.w;
        }
        #pragma unroll
        for (int p = 0; p < 2; p++) {
            int k = bkr + p * 16;
            float4 bv = *(const float4*)&Bm[(size_t)(kt + k) * 64 + bn4 * 4];
            sB2[k][bn4]      = pack2(bv.x, bv.x);
            sB2[k][16 + bn4] = pack2(bv.y, bv.y);
            sB2[k][32 + bn4] = pack2(bv.z, bv.z);
            sB2[k][48 + bn4] = pack2(bv.w, bv.w);
        }
        __syncthreads();
        #pragma unroll
        for (int k = 0; k < 32; k++) {
            const ull* pa = (const ull*)&sA[k][ty * 8];
            ull a0 = pa[0], a1 = pa[1], a2 = pa[2], a3 = pa[3];
            const ull* pb = &sB2[k][0];
            ull bs0 = pb[tx], bs1 = pb[16 + tx], bs2 = pb[32 + tx], bs3 = pb[48 + tx];
            ffma2(acc[0][0], a0, bs0); ffma2(acc[0][1], a0, bs1); ffma2(acc[0][2], a0, bs2); ffma2(acc[0][3], a0, bs3);
            ffma2(acc[1][0], a1, bs0); ffma2(acc[1][1], a1, bs1); ffma2(acc[1][2], a1, bs2); ffma2(acc[1][3], a1, bs3);
            ffma2(acc[2][0], a2, bs0); ffma2(acc[2][1], a2, bs1); ffma2(acc[2][2], a2, bs2); ffma2(acc[2][3], a2, bs3);
            ffma2(acc[3][0], a3, bs0); ffma2(acc[3][1], a3, bs1); ffma2(acc[3][2], a3, bs2); ffma2(acc[3][3], a3, bs3);
        }
        __syncthreads();
    }

    float b4[4];
    #pragma unroll
    for (int j = 0; j < 4; j++) b4[j] = bias[tx * 4 + j];

    #pragma unroll
    for (int mp = 0; mp < 4; mp++) {
        float clo[4], chi[4];
        #pragma unroll
        for (int j = 0; j < 4; j++) {
            float2 v = unpack2(acc[mp][j]);
            clo[j] = lrelu(v.x + b4[j]);
            chi[j] = lrelu(v.y + b4[j]);
        }
        float sl  = clo[0]*clo[0] + clo[1]*clo[1] + clo[2]*clo[2] + clo[3]*clo[3];
        float sh2 = chi[0]*chi[0] + chi[1]*chi[1] + chi[2]*chi[2] + chi[3]*chi[3];
        #pragma unroll
        for (int o = 1; o < 16; o <<= 1) {
            sl  += __shfl_xor_sync(0xffffffffu, sl,  o);
            sh2 += __shfl_xor_sync(0xffffffffu, sh2, o);
        }
        float il = rsqrtf(fmaxf(sl,  1e-24f));
        float ih = rsqrtf(fmaxf(sh2, 1e-24f));
        int rl = m0 + ty * 8 + mp * 2;
        if (rl < NI) {
            float4 o4 = make_float4(clo[0]*il, clo[1]*il, clo[2]*il, clo[3]*il);
            *(float4*)&C[(size_t)rl * 64 + tx * 4] = o4;
        }
        if (rl + 1 < NI) {
            float4 o4 = make_float4(chi[0]*ih, chi[1]*ih, chi[2]*ih, chi[3]*ih);
            *(float4*)&C[(size_t)(rl + 1) * 64 + tx * 4] = o4;
        }
    }
}

// pref rows of xm[mod] = l2norm(input) (NU rows). Warp per row.
__global__ void k_l2norm_pref(const float* __restrict__ in, int mod) {
    int row = blockIdx.x * 8 + (threadIdx.x >> 5);
    if (row >= NU) return;
    float* p = g_xm + (size_t)mod * NN * D + (size_t)row * D;
    int lane = threadIdx.x & 31;
    float a = in[(size_t)row * 64 + lane];
    float b = in[(size_t)row * 64 + 32 + lane];
    float ss = a * a + b * b;
    #pragma unroll
    for (int o = 16; o; o >>= 1) ss += __shfl_xor_sync(0xffffffffu, ss, o);
    float inv = rsqrtf(fmaxf(ss, 1e-24f));
    p[lane]      = a * inv;
    p[32 + lane] = b * inv;
}

// g_hx slot0 = l2norm(id_emb) (NN rows).
__global__ void k_l2norm_x(const float* __restrict__ in) {
    int row = blockIdx.x * 8 + (threadIdx.x >> 5);
    if (row >= NN) return;
    int lane = threadIdx.x & 31;
    float a = in[(size_t)row * 64 + lane];
    float b = in[(size_t)row * 64 + 32 + lane];
    float ss = a * a + b * b;
    #pragma unroll
    for (int o = 16; o; o >>= 1) ss += __shfl_xor_sync(0xffffffffu, ss, o);
    float inv = rsqrtf(fmaxf(ss, 1e-24f));
    g_hx[(size_t)row * 64 + lane]      = a * inv;
    g_hx[(size_t)row * 64 + 32 + lane] = b * inv;
}

// ------------------- GAT (single-pass softmax, half-warp per dst node) -------------------
// mode 0 (routing): nodes [0,NU); in-place pref = l2norm(pref + (Σ e v)/(s+eps)).
// mode 1 (final):   nodes [0,NN); store g_e, alpha = e/(2s+eps);
//                   out[n, 64+modoff+*] = x + lrelu(2/(2s+eps) * Σ e v).
__global__ void k_gat_node(int mod, int nNodes, int mode, float* __restrict__ out, int modoff) {
    int n = blockIdx.x * 16 + (threadIdx.x >> 4);
    if (n >= nNodes) return;
    int lane = threadIdx.x & 15;
    unsigned mask = 0xFFFFu << (threadIdx.x & 16);
    float* xbase = g_xm + (size_t)mod * NN * D;
    int beg = g_offG[n];
    int end = beg + g_degG[n];

    float4 xd = *(const float4*)&xbase[(size_t)n * 64 + lane * 4];

    float s = 0.f;
    float4 acc = make_float4(0.f, 0.f, 0.f, 0.f);
    for (int p = beg; p < end; p++) {
        int src = g_csrG_src[p];
        float4 v = *(const float4*)&xbase[(size_t)src * 64 + lane * 4];
        float dt = xd.x * v.x + xd.y * v.y + xd.z * v.z + xd.w * v.w;
        dt += __shfl_xor_sync(mask, dt, 1);
        dt += __shfl_xor_sync(mask, dt, 2);
        dt += __shfl_xor_sync(mask, dt, 4);
        dt += __shfl_xor_sync(mask, dt, 8);
        float ex = __expf(dt);
        if (mode == 1 && lane == 0) g_e[p] = ex;
        s += ex;
        acc.x += ex * v.x;
        acc.y += ex * v.y;
        acc.z += ex * v.z;
        acc.w += ex * v.w;
    }

    if (mode == 0) {
        float invs = 1.f / (s + 1e-16f);
        float nx = xd.x + acc.x * invs;
        float ny = xd.y + acc.y * invs;
        float nz = xd.z + acc.z * invs;
        float nw = xd.w + acc.w * invs;
        float ss = nx * nx + ny * ny + nz * nz + nw * nw;
        ss += __shfl_xor_sync(mask, ss, 1);
        ss += __shfl_xor_sync(mask, ss, 2);
        ss += __shfl_xor_sync(mask, ss, 4);
        ss += __shfl_xor_sync(mask, ss, 8);
        float inv = rsqrtf(fmaxf(ss, 1e-24f));
        float4 o4 = make_float4(nx * inv, ny * inv, nz * inv, nw * inv);
        *(float4*)&xbase[(size_t)n * 64 + lane * 4] = o4;
    } else {
        float inv2 = 1.f / (2.f * s + 1e-16f);
        float* alpha = g_alpha + (size_t)mod * E;
        __syncwarp(mask);
        for (int p = beg + lane; p < end; p += 16)
            alpha[p] = g_e[p] * inv2;
        float sc = inv2 + inv2;
        float4 o4;
        o4.x = xd.x + lrelu(acc.x * sc);
        o4.y = xd.y + lrelu(acc.y * sc);
        o4.z = xd.z + lrelu(acc.z * sc);
        o4.w = xd.w + lrelu(acc.w * sc);
        *(float4*)&out[(size_t)n * OD + 64 + modoff + lane * 4] = o4;
    }
}

// Combined SAGE weight per CSR slot.
__global__ void k_weight(const float* __restrict__ conf) {
    int p = blockIdx.x * blockDim.x + threadIdx.x;
    if (p >= E) return;
    int src = g_csrG_src[p];
    float wv = g_alpha[p];
    float wt = g_alpha[E + p];
    float w = fmaxf(fmaxf(wv * conf[2 * src], wt * conf[2 * src + 1]), 0.f);
    g_wc[p] = w;
}

// SAGE gather over GAT CSR, half-warp per node.
__global__ void k_sage_node(int layer, float* __restrict__ out) {
    int n = blockIdx.x * 16 + (threadIdx.x >> 4);
    if (n >= NN) return;
    const float* xin = g_hx + (size_t)(layer - 1) * NN * D;
    int lane = threadIdx.x & 15;
    int beg = g_offG[n];
    int cnt = g_degG[n];
    float4 acc = make_float4(0.f, 0.f, 0.f, 0.f);
    for (int p = beg; p < beg + cnt; p++) {
        float w = g_wc[p];
        if (w != 0.f) {
            int src = g_csrG_src[p];
            float4 v = *(const float4*)&xin[(size_t)src * 64 + lane * 4];
            acc.x += w * v.x;
            acc.y += w * v.y;
            acc.z += w * v.z;
            acc.w += w * v.w;
        }
    }
    float invd = 1.f / fmaxf((float)cnt, 1.f);
    float4 h;
    h.x = lrelu(acc.x * invd);
    h.y = lrelu(acc.y * invd);
    h.z = lrelu(acc.z * invd);
    h.w = lrelu(acc.w * invd);
    if (layer == 1) {
        *(float4*)&g_hx[(size_t)NN * D + (size_t)n * 64 + lane * 4] = h;
    } else {
        float4 x0 = *(const float4*)&g_hx[(size_t)n * 64 + lane * 4];
        float4 h1 = *(const float4*)&g_hx[(size_t)NN * D + (size_t)n * 64 + lane * 4];
        float4 o4 = make_float4(x0.x + h1.x + h.x, x0.y + h1.y + h.y,
                                x0.z + h1.z + h.z, x0.w + h1.w + h.w);
        *(float4*)&out[(size_t)n * OD + lane * 4] = o4;
    }
}

// ------------------- launch -------------------
extern "C" void kernel_launch(void* const* d_in, const int* in_sizes, int n_in,
                              void* d_out, int out_size) {
    const void* ei = nullptr;
    const float *v_feat = 0, *t_feat = 0, *pref_v = 0, *pref_t = 0;
    const float *W_v = 0, *b_v = 0, *W_t = 0, *b_t = 0, *id_emb = 0, *conf = 0;
    for (int i = 0; i < n_in; i++) {
        long long sz = in_sizes[i];
        const void* p = d_in[i];
        switch (sz) {
            case 2000000LL:  ei = p; break;
            case 81920000LL: v_feat = (const float*)p; break;
            case 15360000LL: t_feat = (const float*)p; break;
            case 3200000LL:  if (!pref_v) pref_v = (const float*)p; else pref_t = (const float*)p; break;
            case 131072LL:   W_v = (const float*)p; break;
            case 24576LL:    W_t = (const float*)p; break;
            case 64LL:       if (!b_v) b_v = (const float*)p; else b_t = (const float*)p; break;
            case 5760000LL:  id_emb = (const float*)p; break;
            case 180000LL:   conf = (const float*)p; break;
            default: break;
        }
    }
    float* out = (float*)d_out;

    const int B = 256;
    const int gridNodeAll = divup(NN, 16);
    const int gridNodeU   = divup(NU, 16);
    const int nScanB      = divup(NN, 1024);

    k_sniff<<<1, 32>>>((const int*)ei);
    k_zero <<<divup(NN, B), B>>>();
    k_build<<<divup(E, B), B>>>(ei);
    k_scan1<<<nScanB, 1024>>>();
    k_scan2<<<1, 128>>>(nScanB);
    k_scan3<<<nScanB, 1024>>>();
    k_place<<<divup(E, B), B>>>();

    for (int mod = 0; mod < 2; mod++) {
        const float* feat_in = mod == 0 ? v_feat : t_feat;
        const float* W       = mod == 0 ? W_v : W_t;
        const float* bias    = mod == 0 ? b_v : b_t;
        const float* pref_in = mod == 0 ? pref_v : pref_t;
        int K = mod == 0 ? 2048 : 384;

        k_gemm_fused<<<divup(NI, 128), 256>>>(feat_in, W, bias, mod, K);
        k_l2norm_pref<<<divup(NU, 8), 256>>>(pref_in, mod);

        for (int it = 0; it < 3; it++)
            k_gat_node<<<gridNodeU, 256>>>(mod, NU, 0, nullptr, 0);

        k_gat_node<<<gridNodeAll, 256>>>(mod, NN, 1, out, mod * 64);
    }

    k_weight<<<divup(E, B), B>>>(conf);

    k_l2norm_x<<<divup(NN, 8), 256>>>(id_emb);
    k_sage_node<<<gridNodeAll, 256>>>(1, nullptr);
    k_sage_node<<<gridNodeAll, 256>>>(2, out);
}

// round 10
// speedup vs baseline: 1.4722x; 1.4722x over previous
#include <cuda_runtime.h>
#include <math.h>

#define NU 50000
#define NI 40000
#define NN 90000
#define D  64
#define EH 500000
#define E  1000000
#define OD 192

typedef unsigned long long ull;

// ------------------- scratch (static device globals; no allocation) -------------------
__device__ int   g_is64;
__device__ int   g_src[E];
__device__ int   g_dst[E];
__device__ int   g_degG[NN];
__device__ int   g_offG[NN];
__device__ int   g_curG[NN];
__device__ int   g_bsum[128];
__device__ int   g_csrG_src[E];
__device__ float g_e[E];           // exp(logit) per CSR slot (final GAT only)
__device__ float g_alpha[2 * E];   // [mod*E + slot] final-GAT half-alpha
__device__ float g_wc[E];          // combined SAGE weight per CSR slot
__device__ __align__(16) float g_xm[2 * NN * D];
__device__ __align__(16) float g_hx[2 * NN * D];

__device__ __forceinline__ float lrelu(float v) { return v >= 0.f ? v : 0.01f * v; }
static inline int divup(int a, int b) { return (a + b - 1) / b; }

__device__ __forceinline__ void ffma2(ull& d, ull a, ull b) {
    asm("fma.rn.f32x2 %0, %1, %2, %0;" : "+l"(d) : "l"(a), "l"(b));
}
__device__ __forceinline__ ull pack2(float lo, float hi) {
    ull r;
    asm("mov.b64 %0, {%1, %2};" : "=l"(r) : "f"(lo), "f"(hi));
    return r;
}
__device__ __forceinline__ float2 unpack2(ull v) {
    float2 r;
    asm("mov.b64 {%0, %1}, %2;" : "=f"(r.x), "=f"(r.y) : "l"(v));
    return r;
}

// ------------------- edge dtype sniff -------------------
__global__ void k_sniff(const int* __restrict__ ei32) {
    int lane = threadIdx.x;
    int nz = 0;
    for (int i = lane; i < 512; i += 32)
        if (ei32[2 * i + 1] != 0) nz++;
    #pragma unroll
    for (int o = 16; o; o >>= 1) nz += __shfl_xor_sync(0xffffffffu, nz, o);
    if (lane == 0) g_is64 = (nz == 0) ? 1 : 0;
}

// ------------------- graph construction -------------------
__global__ void k_zero() {
    int i = blockIdx.x * blockDim.x + threadIdx.x;
    if (i < NN) g_degG[i] = 0;
}

__global__ void k_build(const void* __restrict__ eiRaw) {
    int i = blockIdx.x * blockDim.x + threadIdx.x;
    if (i >= E) return;
    int s, d;
    if (g_is64) {
        const long long* e64 = (const long long*)eiRaw;
        s = (int)e64[i];
        d = (int)e64[E + i];
    } else {
        const int* e32 = (const int*)eiRaw;
        s = e32[i];
        d = e32[E + i];
    }
    if ((unsigned)s >= NN) s = 0;
    if ((unsigned)d >= NN) d = 0;
    g_src[i] = s;
    g_dst[i] = d;
    atomicAdd(&g_degG[d], 1);
}

__global__ void k_scan1() {
    __shared__ int sh[1024];
    int t = threadIdx.x;
    int i = blockIdx.x * 1024 + t;
    int v = (i < NN) ? g_degG[i] : 0;
    sh[t] = v;
    __syncthreads();
    for (int st = 1; st < 1024; st <<= 1) {
        int x = (t >= st) ? sh[t - st] : 0;
        __syncthreads();
        sh[t] += x;
        __syncthreads();
    }
    if (i < NN) g_offG[i] = sh[t] - v;
    if (t == 1023) g_bsum[blockIdx.x] = sh[1023];
}

__global__ void k_scan2(int nb) {
    __shared__ int sh[128];
    int t = threadIdx.x;
    int v = (t < nb) ? g_bsum[t] : 0;
    sh[t] = v;
    __syncthreads();
    for (int st = 1; st < 128; st <<= 1) {
        int x = (t >= st) ? sh[t - st] : 0;
        __syncthreads();
        sh[t] += x;
        __syncthreads();
    }
    if (t < nb) g_bsum[t] = sh[t] - v;
}

__global__ void k_scan3() {
    int i = blockIdx.x * 1024 + threadIdx.x;
    if (i < NN) {
        int o = g_offG[i] + g_bsum[blockIdx.x];
        g_offG[i] = o;
        g_curG[i] = o;
    }
}

__global__ void k_place() {
    int i = blockIdx.x * blockDim.x + threadIdx.x;
    if (i >= E) return;
    int p = atomicAdd(&g_curG[g_dst[i]], 1);
    if ((unsigned)p < E) g_csrG_src[p] = g_src[i];
}

// ------------------- fused GEMM + bias + leaky + l2norm (R8 version) -------------------
__global__ __launch_bounds__(256) void k_gemm_fused(
    const float* __restrict__ A, const float* __restrict__ Bm,
    const float* __restrict__ bias, int mod, int K)
{
    float* C = g_xm + (size_t)mod * NN * D + (size_t)NU * D;
    __shared__ __align__(16) float sA[32][132];
    __shared__ __align__(16) float sB[32][68];
    int t  = threadIdx.x;
    int tx = t & 15;
    int ty = t >> 4;
    int m0 = blockIdx.x * 128;

    int ak4 = t & 7;
    int ar  = t >> 3;
    int bn4 = t & 15;
    int bkr = t >> 4;

    ull acc[4][4];
    #pragma unroll
    for (int i = 0; i < 4; i++)
        #pragma unroll
        for (int j = 0; j < 4; j++) acc[i][j] = 0ull;

    for (int kt = 0; kt < K; kt += 32) {
        #pragma unroll
        for (int p = 0; p < 4; p++) {
            int m = ar + p * 32;
            int gm = m0 + m;
            float4 av = make_float4(0.f, 0.f, 0.f, 0.f);
            if (gm < NI) av = *(const float4*)&A[(size_t)gm * K + kt + ak4 * 4];
            sA[ak4 * 4 + 0][m] = av.x;
            sA[ak4 * 4 + 1][m] = av.y;
            sA[ak4 * 4 + 2][m] = av.z;
            sA[ak4 * 4 + 3][m] = av.w;
        }
        #pragma unroll
        for (int p = 0; p < 2; p++) {
            int k = bkr + p * 16;
            *(float4*)&sB[k][bn4 * 4] = *(const float4*)&Bm[(size_t)(kt + k) * 64 + bn4 * 4];
        }
        __syncthreads();
        #pragma unroll
        for (int k = 0; k < 32; k++) {
            const ull* pa = (const ull*)&sA[k][ty * 8];
            ull a0 = pa[0], a1 = pa[1], a2 = pa[2], a3 = pa[3];
            float4 b = *(float4*)&sB[k][tx * 4];
            ull bs0 = pack2(b.x, b.x);
            ull bs1 = pack2(b.y, b.y);
            ull bs2 = pack2(b.z, b.z);
            ull bs3 = pack2(b.w, b.w);
            ffma2(acc[0][0], a0, bs0); ffma2(acc[0][1], a0, bs1); ffma2(acc[0][2], a0, bs2); ffma2(acc[0][3], a0, bs3);
            ffma2(acc[1][0], a1, bs0); ffma2(acc[1][1], a1, bs1); ffma2(acc[1][2], a1, bs2); ffma2(acc[1][3], a1, bs3);
            ffma2(acc[2][0], a2, bs0); ffma2(acc[2][1], a2, bs1); ffma2(acc[2][2], a2, bs2); ffma2(acc[2][3], a2, bs3);
            ffma2(acc[3][0], a3, bs0); ffma2(acc[3][1], a3, bs1); ffma2(acc[3][2], a3, bs2); ffma2(acc[3][3], a3, bs3);
        }
        __syncthreads();
    }

    float b4[4];
    #pragma unroll
    for (int j = 0; j < 4; j++) b4[j] = bias[tx * 4 + j];

    #pragma unroll
    for (int mp = 0; mp < 4; mp++) {
        float clo[4], chi[4];
        #pragma unroll
        for (int j = 0; j < 4; j++) {
            float2 v = unpack2(acc[mp][j]);
            clo[j] = lrelu(v.x + b4[j]);
            chi[j] = lrelu(v.y + b4[j]);
        }
        float sl  = clo[0]*clo[0] + clo[1]*clo[1] + clo[2]*clo[2] + clo[3]*clo[3];
        float sh2 = chi[0]*chi[0] + chi[1]*chi[1] + chi[2]*chi[2] + chi[3]*chi[3];
        #pragma unroll
        for (int o = 1; o < 16; o <<= 1) {
            sl  += __shfl_xor_sync(0xffffffffu, sl,  o);
            sh2 += __shfl_xor_sync(0xffffffffu, sh2, o);
        }
        float il = rsqrtf(fmaxf(sl,  1e-24f));
        float ih = rsqrtf(fmaxf(sh2, 1e-24f));
        int rl = m0 + ty * 8 + mp * 2;
        if (rl < NI) {
            float4 o4 = make_float4(clo[0]*il, clo[1]*il, clo[2]*il, clo[3]*il);
            *(float4*)&C[(size_t)rl * 64 + tx * 4] = o4;
        }
        if (rl + 1 < NI) {
            float4 o4 = make_float4(chi[0]*ih, chi[1]*ih, chi[2]*ih, chi[3]*ih);
            *(float4*)&C[(size_t)(rl + 1) * 64 + tx * 4] = o4;
        }
    }
}

// pref rows of xm[mod] = l2norm(input) (NU rows). Warp per row.
__global__ void k_l2norm_pref(const float* __restrict__ in, int mod) {
    int row = blockIdx.x * 8 + (threadIdx.x >> 5);
    if (row >= NU) return;
    float* p = g_xm + (size_t)mod * NN * D + (size_t)row * D;
    int lane = threadIdx.x & 31;
    float a = in[(size_t)row * 64 + lane];
    float b = in[(size_t)row * 64 + 32 + lane];
    float ss = a * a + b * b;
    #pragma unroll
    for (int o = 16; o; o >>= 1) ss += __shfl_xor_sync(0xffffffffu, ss, o);
    float inv = rsqrtf(fmaxf(ss, 1e-24f));
    p[lane]      = a * inv;
    p[32 + lane] = b * inv;
}

// g_hx slot0 = l2norm(id_emb) (NN rows).
__global__ void k_l2norm_x(const float* __restrict__ in) {
    int row = blockIdx.x * 8 + (threadIdx.x >> 5);
    if (row >= NN) return;
    int lane = threadIdx.x & 31;
    float a = in[(size_t)row * 64 + lane];
    float b = in[(size_t)row * 64 + 32 + lane];
    float ss = a * a + b * b;
    #pragma unroll
    for (int o = 16; o; o >>= 1) ss += __shfl_xor_sync(0xffffffffu, ss, o);
    float inv = rsqrtf(fmaxf(ss, 1e-24f));
    g_hx[(size_t)row * 64 + lane]      = a * inv;
    g_hx[(size_t)row * 64 + 32 + lane] = b * inv;
}

// ------------------- GAT (single-pass softmax, WARP per dst node) -------------------
// Σ(e_j/s)v_j = (Σ e_j v_j)/s -> one gather loop accumulates both s and Σ e v.
__global__ void k_gat_node(int mod, int nNodes, int mode, float* __restrict__ out, int modoff) {
    int n = blockIdx.x * 8 + (threadIdx.x >> 5);
    if (n >= nNodes) return;
    float* xbase = g_xm + (size_t)mod * NN * D;
    int lane = threadIdx.x & 31;
    int beg = g_offG[n];
    int end = beg + g_degG[n];

    float2 xd = *(const float2*)&xbase[(size_t)n * D + lane * 2];

    float s = 0.f, ax = 0.f, ay = 0.f;
    for (int p = beg; p < end; p++) {
        int src = g_csrG_src[p];
        float2 v = *(const float2*)&xbase[(size_t)src * D + lane * 2];
        float dt = xd.x * v.x + xd.y * v.y;
        #pragma unroll
        for (int o = 16; o; o >>= 1) dt += __shfl_xor_sync(0xffffffffu, dt, o);
        float ex = __expf(dt);             // identical on all lanes
        if (mode == 1 && lane == 0) g_e[p] = ex;
        s  += ex;
        ax += ex * v.x;
        ay += ex * v.y;
    }

    if (mode == 0) {
        float invs = 1.f / (s + 1e-16f);
        float nx = xd.x + ax * invs;
        float ny = xd.y + ay * invs;
        float ss = nx * nx + ny * ny;
        #pragma unroll
        for (int o = 16; o; o >>= 1) ss += __shfl_xor_sync(0xffffffffu, ss, o);
        float inv = rsqrtf(fmaxf(ss, 1e-24f));
        xbase[(size_t)n * D + lane * 2]     = nx * inv;
        xbase[(size_t)n * D + lane * 2 + 1] = ny * inv;
    } else {
        float inv2 = 1.f / (2.f * s + 1e-16f);
        float* alpha = g_alpha + (size_t)mod * E;
        __syncwarp();
        for (int p = beg + lane; p < end; p += 32)
            alpha[p] = g_e[p] * inv2;
        float sc = inv2 + inv2;            // ei2 duplicates each edge
        int c = lane * 2;
        out[(size_t)n * OD + 64 + modoff + c]     = xd.x + lrelu(ax * sc);
        out[(size_t)n * OD + 64 + modoff + c + 1] = xd.y + lrelu(ay * sc);
    }
}

// Combined SAGE weight per CSR slot.
__global__ void k_weight(const float* __restrict__ conf) {
    int p = blockIdx.x * blockDim.x + threadIdx.x;
    if (p >= E) return;
    int src = g_csrG_src[p];
    float wv = g_alpha[p];
    float wt = g_alpha[E + p];
    float w = fmaxf(fmaxf(wv * conf[2 * src], wt * conf[2 * src + 1]), 0.f);
    g_wc[p] = w;
}

// SAGE gather over GAT CSR, warp per node (R8 version).
__global__ void k_sage_node(int layer, float* __restrict__ out) {
    int n = blockIdx.x * 8 + (threadIdx.x >> 5);
    if (n >= NN) return;
    const float* xin = g_hx + (size_t)(layer - 1) * NN * D;
    int lane = threadIdx.x & 31;
    int beg = g_offG[n];
    int cnt = g_degG[n];
    float ax = 0.f, ay = 0.f;
    for (int p = beg; p < beg + cnt; p++) {
        float w = g_wc[p];
        if (w != 0.f) {
            int src = g_csrG_src[p];
            float2 v = *(const float2*)&xin[(size_t)src * D + lane * 2];
            ax += w * v.x;
            ay += w * v.y;
        }
    }
    float invd = 1.f / fmaxf((float)cnt, 1.f);
    float hx = lrelu(ax * invd), hy = lrelu(ay * invd);
    int c = lane * 2;
    if (layer == 1) {
        g_hx[(size_t)NN * D + (size_t)n * D + c]     = hx;
        g_hx[(size_t)NN * D + (size_t)n * D + c + 1] = hy;
    } else {
        size_t b = (size_t)n * D + c;
        out[(size_t)n * OD + c]     = g_hx[b]     + g_hx[(size_t)NN * D + b]     + hx;
        out[(size_t)n * OD + c + 1] = g_hx[b + 1] + g_hx[(size_t)NN * D + b + 1] + hy;
    }
}

// ------------------- launch -------------------
extern "C" void kernel_launch(void* const* d_in, const int* in_sizes, int n_in,
                              void* d_out, int out_size) {
    const void* ei = nullptr;
    const float *v_feat = 0, *t_feat = 0, *pref_v = 0, *pref_t = 0;
    const float *W_v = 0, *b_v = 0, *W_t = 0, *b_t = 0, *id_emb = 0, *conf = 0;
    for (int i = 0; i < n_in; i++) {
        long long sz = in_sizes[i];
        const void* p = d_in[i];
        switch (sz) {
            case 2000000LL:  ei = p; break;
            case 81920000LL: v_feat = (const float*)p; break;
            case 15360000LL: t_feat = (const float*)p; break;
            case 3200000LL:  if (!pref_v) pref_v = (const float*)p; else pref_t = (const float*)p; break;
            case 131072LL:   W_v = (const float*)p; break;
            case 24576LL:    W_t = (const float*)p; break;
            case 64LL:       if (!b_v) b_v = (const float*)p; else b_t = (const float*)p; break;
            case 5760000LL:  id_emb = (const float*)p; break;
            case 180000LL:   conf = (const float*)p; break;
            default: break;
        }
    }
    float* out = (float*)d_out;

    const int B = 256;
    const int gridNodeAll = divup(NN, 8);
    const int gridNodeU   = divup(NU, 8);
    const int nScanB      = divup(NN, 1024);

    k_sniff<<<1, 32>>>((const int*)ei);
    k_zero <<<divup(NN, B), B>>>();
    k_build<<<divup(E, B), B>>>(ei);
    k_scan1<<<nScanB, 1024>>>();
    k_scan2<<<1, 128>>>(nScanB);
    k_scan3<<<nScanB, 1024>>>();
    k_place<<<divup(E, B), B>>>();

    for (int mod = 0; mod < 2; mod++) {
        const float* feat_in = mod == 0 ? v_feat : t_feat;
        const float* W       = mod == 0 ? W_v : W_t;
        const float* bias    = mod == 0 ? b_v : b_t;
        const float* pref_in = mod == 0 ? pref_v : pref_t;
        int K = mod == 0 ? 2048 : 384;

        k_gemm_fused<<<divup(NI, 128), 256>>>(feat_in, W, bias, mod, K);
        k_l2norm_pref<<<divup(NU, 8), 256>>>(pref_in, mod);

        for (int it = 0; it < 3; it++)
            k_gat_node<<<gridNodeU, 256>>>(mod, NU, 0, nullptr, 0);

        k_gat_node<<<gridNodeAll, 256>>>(mod, NN, 1, out, mod * 64);
    }

    k_weight<<<divup(E, B), B>>>(conf);

    k_l2norm_x<<<divup(NN, 8), 256>>>(id_emb);
    k_sage_node<<<gridNodeAll, 256>>>(1, nullptr);
    k_sage_node<<<gridNodeAll, 256>>>(2, out);
}